// round 15
// baseline (speedup 1.0000x reference)
#include <cuda_runtime.h>
#include <cuda_fp16.h>
#include <math.h>
#include <stdint.h>

#define NN 100000
#define DD 128
#define EE 3200000
#define RCAP 96                            // slots per row bucket (Poisson(32) +11 sigma)
#define AST 136                            // smem row stride (halves), conflict-free ldmatrix

extern __shared__ char dynsm[];

// ---------------- static device scratch ----------------
__device__ __half2 g_h16a[NN * (DD / 2)];
__device__ __half2 g_h16b[NN * (DD / 2)];
__device__ int      g_cnt[3][NN];            // zero-initialized; self-resetting
__device__ unsigned g_epack[3][NN * RCAP];   // packed: col(17) | fp16val(15)
__device__ __half   g_wt[6][DD * DD];        // transposed fp16 weights

__device__ __forceinline__ uint32_t smem_u32(const void* p) {
    uint32_t a;
    asm("{ .reg .u64 t; cvta.to.shared.u64 t, %1; cvt.u32.u64 %0, t; }" : "=r"(a) : "l"(p));
    return a;
}

__device__ __forceinline__ void edec(unsigned p, int& c, float& w) {
    c = (int)(p & 0x1FFFFu);
    w = __half2float(__ushort_as_half((unsigned short)(p >> 17)));
}
__device__ __forceinline__ unsigned eenc(int c, float v) {
    unsigned short hb = __half_as_ushort(__float2half_rn(v));   // sign bit 0 (v >= 0)
    return (unsigned)c | ((unsigned)hb << 17);
}

// ---------------- weight prep: fp16 transpose (6 matrices) ----------------
__global__ void wprep_kernel(const float* __restrict__ hgw, const float* __restrict__ lgw,
                             const float* __restrict__ fw1) {
    int m = blockIdx.y;
    const float* W = (m < 3) ? (hgw + (size_t)m * DD * DD)
                   : (m < 5) ? (lgw + (size_t)(m - 3) * DD * DD)
                             : fw1;
    int i = blockIdx.x * blockDim.x + threadIdx.x;
    if (i >= DD * DD) return;
    int n = i >> 7, k = i & 127;
    g_wt[m][n * DD + k] = __float2half_rn(__ldg(&W[k * DD + n]));
}

// ---------------- MMA linear: Y = half(X @ W + b); tile 128x128x128 ----------------
__global__ void __launch_bounds__(256, 2) mma_linear_kernel(
    const uint4* __restrict__ X, const uint4* __restrict__ Bt,
    const float* __restrict__ bias, __half2* __restrict__ Y)
{
    __half* sm = (__half*)dynsm;
    __half* sA = sm;
    __half* sB = sm + 128 * AST;
    float* bs = (float*)(sm + 2 * 128 * AST);

    const int tid = threadIdx.x;
    const int lane = tid & 31;
    const int warp = tid >> 5;
    const int warpM = warp & 3;
    const int warpN = warp >> 2;
    const int rowBase = blockIdx.x * 128;

    for (int i = tid; i < 2048; i += 256) {
        int r = i >> 4, c = i & 15;
        int gr = rowBase + r;
        uint4 v = (gr < NN) ? __ldg(&X[(size_t)gr * 16 + c]) : make_uint4(0u, 0u, 0u, 0u);
        *(uint4*)&sA[r * AST + c * 8] = v;
    }
    for (int i = tid; i < 2048; i += 256) {
        int r = i >> 4, c = i & 15;
        *(uint4*)&sB[r * AST + c * 8] = __ldg(&Bt[i]);
    }
    if (tid < 128) bs[tid] = bias ? __ldg(&bias[tid]) : 0.f;
    __syncthreads();

    float acc[2][8][4];
#pragma unroll
    for (int mi = 0; mi < 2; mi++)
#pragma unroll
        for (int ni = 0; ni < 8; ni++)
#pragma unroll
            for (int q = 0; q < 4; q++) acc[mi][ni][q] = 0.f;

#pragma unroll
    for (int k0 = 0; k0 < 128; k0 += 16) {
        uint32_t a[2][4];
#pragma unroll
        for (int mi = 0; mi < 2; mi++) {
            int row = warpM * 32 + mi * 16 + (lane & 15);
            int col = k0 + ((lane >> 4) << 3);
            uint32_t addr = smem_u32(&sA[row * AST + col]);
            asm volatile("ldmatrix.sync.aligned.m8n8.x4.shared.b16 {%0,%1,%2,%3}, [%4];"
                         : "=r"(a[mi][0]), "=r"(a[mi][1]), "=r"(a[mi][2]), "=r"(a[mi][3])
                         : "r"(addr));
        }
        uint32_t b[8][2];
#pragma unroll
        for (int ni = 0; ni < 8; ni++) {
            int n = warpN * 64 + ni * 8 + (lane & 7);
            int col = k0 + (((lane >> 3) & 1) << 3);
            uint32_t addr = smem_u32(&sB[n * AST + col]);
            asm volatile("ldmatrix.sync.aligned.m8n8.x2.shared.b16 {%0,%1}, [%2];"
                         : "=r"(b[ni][0]), "=r"(b[ni][1]) : "r"(addr));
        }
#pragma unroll
        for (int mi = 0; mi < 2; mi++)
#pragma unroll
            for (int ni = 0; ni < 8; ni++) {
                asm volatile(
                    "mma.sync.aligned.m16n8k16.row.col.f32.f16.f16.f32 "
                    "{%0,%1,%2,%3}, {%4,%5,%6,%7}, {%8,%9}, {%0,%1,%2,%3};"
                    : "+f"(acc[mi][ni][0]), "+f"(acc[mi][ni][1]),
                      "+f"(acc[mi][ni][2]), "+f"(acc[mi][ni][3])
                    : "r"(a[mi][0]), "r"(a[mi][1]), "r"(a[mi][2]), "r"(a[mi][3]),
                      "r"(b[ni][0]), "r"(b[ni][1]));
            }
    }

    const int g = lane >> 2, t = lane & 3;
#pragma unroll
    for (int mi = 0; mi < 2; mi++) {
#pragma unroll
        for (int ni = 0; ni < 8; ni++) {
            int col = warpN * 64 + ni * 8 + t * 2;
            float b0 = bs[col], b1 = bs[col + 1];
            int r0 = rowBase + warpM * 32 + mi * 16 + g;
            int r1 = r0 + 8;
            if (r0 < NN)
                Y[(size_t)r0 * 64 + (col >> 1)] =
                    __floats2half2_rn(acc[mi][ni][0] + b0, acc[mi][ni][1] + b1);
            if (r1 < NN)
                Y[(size_t)r1 * 64 + (col >> 1)] =
                    __floats2half2_rn(acc[mi][ni][2] + b0, acc[mi][ni][3] + b1);
        }
    }
}

// ------- Fused score+gate: tile = 64 nodes x 2 views (128 MMA rows) -------
__global__ void __launch_bounds__(256, 2) mma_scoregate_kernel(
    const float4* __restrict__ x4,    // fp32 [2N,128]
    const uint4* __restrict__ Bt,     // fw1^T fp16
    const float* __restrict__ b1,
    const float* __restrict__ w2,
    uint4* __restrict__ fused)        // fp16 [N,128]
{
    __half* sm = (__half*)dynsm;
    __half* sA = sm;
    __half* sB = sm + 128 * AST;
    __shared__ float b1s[DD];
    __shared__ float w2s[DD];
    __shared__ float ssc[2][128];

    const int tid = threadIdx.x;
    const int lane = tid & 31;
    const int warp = tid >> 5;
    const int warpM = warp & 3;
    const int warpN = warp >> 2;
    const int nodeBase = blockIdx.x * 64;

    for (int i = tid; i < 2048; i += 256) {
        int r = i >> 4, c = i & 15;
        int view = r >> 6;
        int node = nodeBase + (r & 63);
        uint4 v = make_uint4(0u, 0u, 0u, 0u);
        if (node < NN) {
            size_t gr = (size_t)view * NN + node;
            float4 lo = __ldg(&x4[gr * 32 + c * 2]);
            float4 hi = __ldg(&x4[gr * 32 + c * 2 + 1]);
            __half2 h0 = __floats2half2_rn(lo.x, lo.y);
            __half2 h1 = __floats2half2_rn(lo.z, lo.w);
            __half2 h2 = __floats2half2_rn(hi.x, hi.y);
            __half2 h3 = __floats2half2_rn(hi.z, hi.w);
            v.x = *(unsigned*)&h0; v.y = *(unsigned*)&h1;
            v.z = *(unsigned*)&h2; v.w = *(unsigned*)&h3;
        }
        *(uint4*)&sA[r * AST + c * 8] = v;
    }
    for (int i = tid; i < 2048; i += 256) {
        int r = i >> 4, c = i & 15;
        *(uint4*)&sB[r * AST + c * 8] = __ldg(&Bt[i]);
    }
    if (tid < 128) {
        b1s[tid] = __ldg(&b1[tid]);
        w2s[tid] = __ldg(&w2[tid]);
    }
    __syncthreads();

    float acc[2][8][4];
#pragma unroll
    for (int mi = 0; mi < 2; mi++)
#pragma unroll
        for (int ni = 0; ni < 8; ni++)
#pragma unroll
            for (int q = 0; q < 4; q++) acc[mi][ni][q] = 0.f;

#pragma unroll
    for (int k0 = 0; k0 < 128; k0 += 16) {
        uint32_t a[2][4];
#pragma unroll
        for (int mi = 0; mi < 2; mi++) {
            int row = warpM * 32 + mi * 16 + (lane & 15);
            int col = k0 + ((lane >> 4) << 3);
            uint32_t addr = smem_u32(&sA[row * AST + col]);
            asm volatile("ldmatrix.sync.aligned.m8n8.x4.shared.b16 {%0,%1,%2,%3}, [%4];"
                         : "=r"(a[mi][0]), "=r"(a[mi][1]), "=r"(a[mi][2]), "=r"(a[mi][3])
                         : "r"(addr));
        }
        uint32_t b[8][2];
#pragma unroll
        for (int ni = 0; ni < 8; ni++) {
            int n = warpN * 64 + ni * 8 + (lane & 7);
            int col = k0 + (((lane >> 3) & 1) << 3);
            uint32_t addr = smem_u32(&sB[n * AST + col]);
            asm volatile("ldmatrix.sync.aligned.m8n8.x2.shared.b16 {%0,%1}, [%2];"
                         : "=r"(b[ni][0]), "=r"(b[ni][1]) : "r"(addr));
        }
#pragma unroll
        for (int mi = 0; mi < 2; mi++)
#pragma unroll
            for (int ni = 0; ni < 8; ni++) {
                asm volatile(
                    "mma.sync.aligned.m16n8k16.row.col.f32.f16.f16.f32 "
                    "{%0,%1,%2,%3}, {%4,%5,%6,%7}, {%8,%9}, {%0,%1,%2,%3};"
                    : "+f"(acc[mi][ni][0]), "+f"(acc[mi][ni][1]),
                      "+f"(acc[mi][ni][2]), "+f"(acc[mi][ni][3])
                    : "r"(a[mi][0]), "r"(a[mi][1]), "r"(a[mi][2]), "r"(a[mi][3]),
                      "r"(b[ni][0]), "r"(b[ni][1]));
            }
    }

    const int g = lane >> 2, t = lane & 3;
#pragma unroll
    for (int mi = 0; mi < 2; mi++) {
        float pr0 = 0.f, pr1 = 0.f;
#pragma unroll
        for (int ni = 0; ni < 8; ni++) {
            int col = warpN * 64 + ni * 8 + t * 2;
            float w0 = w2s[col], w1 = w2s[col + 1];
            float c0 = b1s[col], c1 = b1s[col + 1];
            pr0 += tanhf(acc[mi][ni][0] + c0) * w0 + tanhf(acc[mi][ni][1] + c1) * w1;
            pr1 += tanhf(acc[mi][ni][2] + c0) * w0 + tanhf(acc[mi][ni][3] + c1) * w1;
        }
        pr0 += __shfl_xor_sync(0xffffffffu, pr0, 1);
        pr0 += __shfl_xor_sync(0xffffffffu, pr0, 2);
        pr1 += __shfl_xor_sync(0xffffffffu, pr1, 1);
        pr1 += __shfl_xor_sync(0xffffffffu, pr1, 2);
        if (t == 0) {
            ssc[warpN][warpM * 32 + mi * 16 + g] = pr0;
            ssc[warpN][warpM * 32 + mi * 16 + g + 8] = pr1;
        }
    }
    __syncthreads();

    int j = tid >> 2, q = tid & 3;
    int node = nodeBase + j;
    if (node < NN) {
        float s0 = ssc[0][j] + ssc[1][j];
        float s1 = ssc[0][64 + j] + ssc[1][64 + j];
        float m = fmaxf(s0, s1);
        float e0 = expf(s0 - m), e1 = expf(s1 - m);
        float inv = 1.f / (e0 + e1);
        float g0 = e0 * inv, g1 = e1 * inv;
#pragma unroll
        for (int c = q * 4; c < q * 4 + 4; c++) {
            uint4 av = *(uint4*)&sA[j * AST + c * 8];
            uint4 bv = *(uint4*)&sA[(64 + j) * AST + c * 8];
            uint4 o;
            const unsigned* ap = &av.x;
            const unsigned* bp = &bv.x;
            unsigned* op = &o.x;
#pragma unroll
            for (int w = 0; w < 4; w++) {
                float2 fa = __half22float2(*(__half2*)&ap[w]);
                float2 fb = __half22float2(*(__half2*)&bp[w]);
                __half2 h = __floats2half2_rn(g0 * fa.x + g1 * fb.x,
                                              g0 * fa.y + g1 * fb.y);
                op[w] = *(unsigned*)&h;
            }
            fused[(size_t)node * 16 + c] = o;
        }
    }
}

// ---------------- direct scatter into padded row buckets (R13 body, plain stores) ----
__global__ void scatter1_kernel(const int* __restrict__ rows, const int* __restrict__ cols,
                                const float* __restrict__ vals, int m) {
    int* cnt = g_cnt[m];
    unsigned* epack = g_epack[m];
    int i = (blockIdx.x * blockDim.x + threadIdx.x) * 8;
    if (i + 7 < EE) {
        int4 rA = __ldg((const int4*)(rows + i));
        int4 rB = __ldg((const int4*)(rows + i + 4));
        int4 cA = __ldg((const int4*)(cols + i));
        int4 cB = __ldg((const int4*)(cols + i + 4));
        float4 vA = __ldg((const float4*)(vals + i));
        float4 vB = __ldg((const float4*)(vals + i + 4));
        int p0 = atomicAdd(&cnt[rA.x], 1);
        int p1 = atomicAdd(&cnt[rA.y], 1);
        int p2 = atomicAdd(&cnt[rA.z], 1);
        int p3 = atomicAdd(&cnt[rA.w], 1);
        int p4 = atomicAdd(&cnt[rB.x], 1);
        int p5 = atomicAdd(&cnt[rB.y], 1);
        int p6 = atomicAdd(&cnt[rB.z], 1);
        int p7 = atomicAdd(&cnt[rB.w], 1);
        epack[(size_t)rA.x * RCAP + p0] = eenc(cA.x, vA.x);
        epack[(size_t)rA.y * RCAP + p1] = eenc(cA.y, vA.y);
        epack[(size_t)rA.z * RCAP + p2] = eenc(cA.z, vA.z);
        epack[(size_t)rA.w * RCAP + p3] = eenc(cA.w, vA.w);
        epack[(size_t)rB.x * RCAP + p4] = eenc(cB.x, vB.x);
        epack[(size_t)rB.y * RCAP + p5] = eenc(cB.y, vB.y);
        epack[(size_t)rB.z * RCAP + p6] = eenc(cB.z, vB.z);
        epack[(size_t)rB.w * RCAP + p7] = eenc(cB.w, vB.w);
    } else {
        for (int j = i; j < EE; j++) {
            int rr = rows[j];
            int p = atomicAdd(&cnt[rr], 1);
            epack[(size_t)rr * RCAP + p] = eenc(cols[j], vals[j]);
        }
    }
}

// ---------------- SpMM: warp per row, bucket layout, packed 4B meta ----------
// addH: optional fp16 vector added into acc epilogue
// resetCnt: last user of this matrix zeroes cnt for the next graph replay
__global__ void spmm_kernel(int* __restrict__ cnt, const unsigned* __restrict__ ep,
                            const uint4* __restrict__ x,
                            float* __restrict__ yF, uint2* __restrict__ yH,
                            float* __restrict__ acc, const uint2* __restrict__ addH,
                            int relu, int resetCnt) {
    int gwarp = (blockIdx.x * blockDim.x + threadIdx.x) >> 5;
    int lane  = threadIdx.x & 31;
    int hr = lane >> 4;        // half-warp id
    int li = lane & 15;        // 16B chunk within row
    int beg = gwarp * RCAP;
    int end = beg + cnt[gwarp];
    if (resetCnt && lane == 0) cnt[gwarp] = 0;

    float a8[8];
#pragma unroll
    for (int k = 0; k < 8; k++) a8[k] = 0.f;

    int e = beg;
    // main: 4 edges/iter; each half-warp loads ONE uint2 = its two packed edges
    for (; e + 3 < end; e += 4) {
        uint2 mm = __ldg((const uint2*)&ep[e + 2 * hr]);
        int c0, c1; float w0, w1;
        edec(mm.x, c0, w0);
        edec(mm.y, c1, w1);
        uint4 v0 = __ldg(&x[(size_t)c0 * 16 + li]);
        uint4 v1 = __ldg(&x[(size_t)c1 * 16 + li]);
        float2 f0 = __half22float2(*(__half2*)&v0.x);
        float2 f1 = __half22float2(*(__half2*)&v0.y);
        float2 f2 = __half22float2(*(__half2*)&v0.z);
        float2 f3 = __half22float2(*(__half2*)&v0.w);
        a8[0] += w0 * f0.x; a8[1] += w0 * f0.y; a8[2] += w0 * f1.x; a8[3] += w0 * f1.y;
        a8[4] += w0 * f2.x; a8[5] += w0 * f2.y; a8[6] += w0 * f3.x; a8[7] += w0 * f3.y;
        f0 = __half22float2(*(__half2*)&v1.x);
        f1 = __half22float2(*(__half2*)&v1.y);
        f2 = __half22float2(*(__half2*)&v1.z);
        f3 = __half22float2(*(__half2*)&v1.w);
        a8[0] += w1 * f0.x; a8[1] += w1 * f0.y; a8[2] += w1 * f1.x; a8[3] += w1 * f1.y;
        a8[4] += w1 * f2.x; a8[5] += w1 * f2.y; a8[6] += w1 * f3.x; a8[7] += w1 * f3.y;
    }
    // 2-edge tail
    for (; e + 1 < end; e += 2) {
        unsigned mm = __ldg(&ep[e + hr]);
        int c0; float w0;
        edec(mm, c0, w0);
        uint4 v0 = __ldg(&x[(size_t)c0 * 16 + li]);
        float2 f0 = __half22float2(*(__half2*)&v0.x);
        float2 f1 = __half22float2(*(__half2*)&v0.y);
        float2 f2 = __half22float2(*(__half2*)&v0.z);
        float2 f3 = __half22float2(*(__half2*)&v0.w);
        a8[0] += w0 * f0.x; a8[1] += w0 * f0.y; a8[2] += w0 * f1.x; a8[3] += w0 * f1.y;
        a8[4] += w0 * f2.x; a8[5] += w0 * f2.y; a8[6] += w0 * f3.x; a8[7] += w0 * f3.y;
    }
    // final single edge
    if (e < end && hr == 0) {
        unsigned mm = __ldg(&ep[e]);
        int c0; float w0;
        edec(mm, c0, w0);
        uint4 v0 = __ldg(&x[(size_t)c0 * 16 + li]);
        float2 f0 = __half22float2(*(__half2*)&v0.x);
        float2 f1 = __half22float2(*(__half2*)&v0.y);
        float2 f2 = __half22float2(*(__half2*)&v0.z);
        float2 f3 = __half22float2(*(__half2*)&v0.w);
        a8[0] += w0 * f0.x; a8[1] += w0 * f0.y; a8[2] += w0 * f1.x; a8[3] += w0 * f1.y;
        a8[4] += w0 * f2.x; a8[5] += w0 * f2.y; a8[6] += w0 * f3.x; a8[7] += w0 * f3.y;
    }

#pragma unroll
    for (int k = 0; k < 8; k++) a8[k] += __shfl_xor_sync(0xffffffffu, a8[k], 16);

    float4 r;
    r.x = a8[hr * 4 + 0]; r.y = a8[hr * 4 + 1];
    r.z = a8[hr * 4 + 2]; r.w = a8[hr * 4 + 3];
    if (relu) {
        r.x = fmaxf(r.x, 0.f); r.y = fmaxf(r.y, 0.f);
        r.z = fmaxf(r.z, 0.f); r.w = fmaxf(r.w, 0.f);
    }
    size_t oi = (size_t)gwarp * 32 + li * 2 + hr;
    if (yF) ((float4*)yF)[oi] = r;
    if (yH) {
        __half2 h0 = __floats2half2_rn(r.x, r.y);
        __half2 h1 = __floats2half2_rn(r.z, r.w);
        uint2 hv;
        hv.x = *(unsigned*)&h0; hv.y = *(unsigned*)&h1;
        yH[oi] = hv;
    }
    if (acc) {
        float4 o = ((float4*)acc)[oi];
        if (addH) {
            uint2 av = __ldg(&addH[oi]);
            float2 a0 = __half22float2(*(__half2*)&av.x);
            float2 a1 = __half22float2(*(__half2*)&av.y);
            o.x += a0.x; o.y += a0.y; o.z += a1.x; o.w += a1.y;
        }
        o.x += r.x; o.y += r.y; o.z += r.z; o.w += r.w;
        ((float4*)acc)[oi] = o;
    }
}

// ---------------- host ----------------
extern "C" void kernel_launch(void* const* d_in, const int* in_sizes, int n_in,
                              void* d_out, int out_size) {
    const float* x    = (const float*)d_in[0];
    const float* fw1  = (const float*)d_in[1];
    const float* fb1  = (const float*)d_in[2];
    const float* fw2  = (const float*)d_in[3];
    const float* fb2  = (const float*)d_in[4];
    const float* hgw  = (const float*)d_in[5];
    const float* lgw  = (const float*)d_in[6];
    const float* lgb  = (const float*)d_in[7];
    const float* c1v  = (const float*)d_in[8];
    const float* c2v  = (const float*)d_in[9];
    const float* lgv  = (const float*)d_in[10];
    const int* c1r = (const int*)d_in[11];
    const int* c1c = (const int*)d_in[12];
    const int* c2r = (const int*)d_in[13];
    const int* c2c = (const int*)d_in[14];
    const int* lgr = (const int*)d_in[15];
    const int* lgc = (const int*)d_in[16];
    float* out  = (float*)d_out;              // [2N, D]
    float* out2 = out + (size_t)NN * DD;
    (void)fb2;                                 // softmax-invariant

    __half2 *h16a, *h16b;
    int *cntBase;
    unsigned *epackBase;
    __half *wtBase;
    cudaGetSymbolAddress((void**)&h16a, g_h16a);
    cudaGetSymbolAddress((void**)&h16b, g_h16b);
    cudaGetSymbolAddress((void**)&cntBase, g_cnt);
    cudaGetSymbolAddress((void**)&epackBase, g_epack);
    cudaGetSymbolAddress((void**)&wtBase, g_wt);

    int* cnt[3];
    unsigned* epack[3];
    for (int m = 0; m < 3; m++) {
        cnt[m]   = cntBase + (size_t)m * NN;
        epack[m] = epackBase + (size_t)m * NN * RCAP;
    }
    const uint4* wt[6];
    for (int m = 0; m < 6; m++) wt[m] = (const uint4*)(wtBase + (size_t)m * DD * DD);

    const size_t smemMMA = 2 * 128 * AST * sizeof(__half) + DD * sizeof(float);   // ~70 KB
    cudaFuncSetAttribute(mma_linear_kernel, cudaFuncAttributeMaxDynamicSharedMemorySize, (int)smemMMA);
    cudaFuncSetAttribute(mma_scoregate_kernel, cudaFuncAttributeMaxDynamicSharedMemorySize, (int)smemMMA);

    const int SPB = (NN * 32 + 127) / 128;    // spmm: 128-thread blocks (4 warps)
    const int MB  = (NN + 127) / 128;         // mma tile grid
    const int SG  = (NN + 63) / 64;           // scoregate grid

    // ---- lazily-created side stream + events (host-side resources only) ----
    static cudaStream_t sCsr = nullptr;
    static cudaEvent_t evFork = nullptr, evC1 = nullptr, evC2 = nullptr, evC3 = nullptr;
    if (sCsr == nullptr) {
        cudaStreamCreateWithFlags(&sCsr, cudaStreamNonBlocking);
        cudaEventCreateWithFlags(&evFork, cudaEventDisableTiming);
        cudaEventCreateWithFlags(&evC1, cudaEventDisableTiming);
        cudaEventCreateWithFlags(&evC2, cudaEventDisableTiming);
        cudaEventCreateWithFlags(&evC3, cudaEventDisableTiming);
    }

    // fork the bucket-build stream off the main (capture) stream
    cudaEventRecord(evFork, 0);
    cudaStreamWaitEvent(sCsr, evFork, 0);

    // ---- bucket builds (per matrix) on side stream; cnt self-resets in spmm ----
    const int* rr[3] = { c1r, c2r, lgr };
    const int* cc[3] = { c1c, c2c, lgc };
    const float* vv[3] = { c1v, c2v, lgv };
    cudaEvent_t evDone[3] = { evC1, evC2, evC3 };
    for (int m = 0; m < 3; m++) {
        scatter1_kernel<<<(EE / 8 + 255) / 256, 256, 0, sCsr>>>(rr[m], cc[m], vv[m], m);
        cudaEventRecord(evDone[m], sCsr);
    }

    // ---- main stream: weight prep + fused score/gate -> h16b ----
    wprep_kernel<<<dim3(64, 6), 256>>>(hgw, lgw, fw1);
    mma_scoregate_kernel<<<SG, 256, smemMMA>>>((const float4*)x, wt[5], fb1, fw2, (uint4*)h16b);

    // ---- HypergraphConv ----
    mma_linear_kernel<<<MB, 256, smemMMA>>>((const uint4*)h16b, wt[0], nullptr, h16a);
    cudaStreamWaitEvent(0, evC1, 0);          // coef1 buckets ready
    spmm_kernel<<<SPB, 128>>>(cnt[0], epack[0], (const uint4*)h16a, nullptr, (uint2*)h16b, nullptr, nullptr, 1, 0);
    mma_linear_kernel<<<MB, 256, smemMMA>>>((const uint4*)h16b, wt[1], nullptr, h16a);
    spmm_kernel<<<SPB, 128>>>(cnt[0], epack[0], (const uint4*)h16a, nullptr, (uint2*)h16b, nullptr, nullptr, 1, 0);
    mma_linear_kernel<<<MB, 256, smemMMA>>>((const uint4*)h16b, wt[2], nullptr, h16a);
    // h -> out (fp32) + fp16 shadow h16b; LAST coef1 user -> reset cnt[0]
    spmm_kernel<<<SPB, 128>>>(cnt[0], epack[0], (const uint4*)h16a, out, (uint2*)h16b, nullptr, nullptr, 1, 1);
    cudaStreamWaitEvent(0, evC2, 0);          // coef2 buckets ready
    // y = relu(spmm(coef2, h)): y fp32 -> out2 (init), y fp16 -> h16a; reset cnt[1]
    spmm_kernel<<<SPB, 128>>>(cnt[1], epack[1], (const uint4*)h16b, out2, (uint2*)h16a, nullptr, nullptr, 1, 1);

    // ---- LineConv ----
    mma_linear_kernel<<<MB, 256, smemMMA>>>((const uint4*)h16a, wt[3], lgb, h16b);
    cudaStreamWaitEvent(0, evC3, 0);          // lg buckets ready
    // cur1 -> h16a (fp16 only, no RMW)
    spmm_kernel<<<SPB, 128>>>(cnt[2], epack[2], (const uint4*)h16b, nullptr, (uint2*)h16a, nullptr, nullptr, 0, 0);
    mma_linear_kernel<<<MB, 256, smemMMA>>>((const uint4*)h16a, wt[4], lgb + DD, h16b);
    // cur2 + fused final accumulation: out2 = out2(y) + cur1(h16a) + cur2; reset cnt[2]
    spmm_kernel<<<SPB, 128>>>(cnt[2], epack[2], (const uint4*)h16b, nullptr, nullptr, out2, (const uint2*)h16a, 0, 1);
}

// round 16
// speedup vs baseline: 1.5189x; 1.5189x over previous
#include <cuda_runtime.h>
#include <cuda_fp16.h>
#include <math.h>
#include <stdint.h>

#define NN 100000
#define DD 128
#define EE 3200000
#define RCAP 96                            // slots per row bucket (Poisson(32) +11 sigma)
#define AST 136                            // smem row stride (halves), conflict-free ldmatrix

extern __shared__ char dynsm[];

// ---------------- static device scratch ----------------
__device__ __half2 g_h16a[NN * (DD / 2)];
__device__ __half2 g_h16b[NN * (DD / 2)];
__device__ int      g_cnt[3][NN];
__device__ unsigned g_epack[3][NN * RCAP];   // packed: col(17) | fp16val(15)
__device__ __half   g_wt[6][DD * DD];        // transposed fp16 weights

__device__ __forceinline__ uint32_t smem_u32(const void* p) {
    uint32_t a;
    asm("{ .reg .u64 t; cvta.to.shared.u64 t, %1; cvt.u32.u64 %0, t; }" : "=r"(a) : "l"(p));
    return a;
}

__device__ __forceinline__ void edec(unsigned p, int& c, float& w) {
    c = (int)(p & 0x1FFFFu);
    w = __half2float(__ushort_as_half((unsigned short)(p >> 17)));
}
__device__ __forceinline__ unsigned eenc(int c, float v) {
    unsigned short hb = __half_as_ushort(__float2half_rn(v));   // sign bit 0 (v >= 0)
    return (unsigned)c | ((unsigned)hb << 17);
}

// ---------------- weight prep: fp16 transpose (6 matrices) ----------------
__global__ void wprep_kernel(const float* __restrict__ hgw, const float* __restrict__ lgw,
                             const float* __restrict__ fw1) {
    int m = blockIdx.y;
    const float* W = (m < 3) ? (hgw + (size_t)m * DD * DD)
                   : (m < 5) ? (lgw + (size_t)(m - 3) * DD * DD)
                             : fw1;
    int i = blockIdx.x * blockDim.x + threadIdx.x;
    if (i >= DD * DD) return;
    int n = i >> 7, k = i & 127;
    g_wt[m][n * DD + k] = __float2half_rn(__ldg(&W[k * DD + n]));
}

// ---------------- MMA linear: Y = half(X @ W + b); tile 128x128x128 ----------------
__global__ void __launch_bounds__(256, 2) mma_linear_kernel(
    const uint4* __restrict__ X, const uint4* __restrict__ Bt,
    const float* __restrict__ bias, __half2* __restrict__ Y)
{
    __half* sm = (__half*)dynsm;
    __half* sA = sm;
    __half* sB = sm + 128 * AST;
    float* bs = (float*)(sm + 2 * 128 * AST);

    const int tid = threadIdx.x;
    const int lane = tid & 31;
    const int warp = tid >> 5;
    const int warpM = warp & 3;
    const int warpN = warp >> 2;
    const int rowBase = blockIdx.x * 128;

    for (int i = tid; i < 2048; i += 256) {
        int r = i >> 4, c = i & 15;
        int gr = rowBase + r;
        uint4 v = (gr < NN) ? __ldg(&X[(size_t)gr * 16 + c]) : make_uint4(0u, 0u, 0u, 0u);
        *(uint4*)&sA[r * AST + c * 8] = v;
    }
    for (int i = tid; i < 2048; i += 256) {
        int r = i >> 4, c = i & 15;
        *(uint4*)&sB[r * AST + c * 8] = __ldg(&Bt[i]);
    }
    if (tid < 128) bs[tid] = bias ? __ldg(&bias[tid]) : 0.f;
    __syncthreads();

    float acc[2][8][4];
#pragma unroll
    for (int mi = 0; mi < 2; mi++)
#pragma unroll
        for (int ni = 0; ni < 8; ni++)
#pragma unroll
            for (int q = 0; q < 4; q++) acc[mi][ni][q] = 0.f;

#pragma unroll
    for (int k0 = 0; k0 < 128; k0 += 16) {
        uint32_t a[2][4];
#pragma unroll
        for (int mi = 0; mi < 2; mi++) {
            int row = warpM * 32 + mi * 16 + (lane & 15);
            int col = k0 + ((lane >> 4) << 3);
            uint32_t addr = smem_u32(&sA[row * AST + col]);
            asm volatile("ldmatrix.sync.aligned.m8n8.x4.shared.b16 {%0,%1,%2,%3}, [%4];"
                         : "=r"(a[mi][0]), "=r"(a[mi][1]), "=r"(a[mi][2]), "=r"(a[mi][3])
                         : "r"(addr));
        }
        uint32_t b[8][2];
#pragma unroll
        for (int ni = 0; ni < 8; ni++) {
            int n = warpN * 64 + ni * 8 + (lane & 7);
            int col = k0 + (((lane >> 3) & 1) << 3);
            uint32_t addr = smem_u32(&sB[n * AST + col]);
            asm volatile("ldmatrix.sync.aligned.m8n8.x2.shared.b16 {%0,%1}, [%2];"
                         : "=r"(b[ni][0]), "=r"(b[ni][1]) : "r"(addr));
        }
#pragma unroll
        for (int mi = 0; mi < 2; mi++)
#pragma unroll
            for (int ni = 0; ni < 8; ni++) {
                asm volatile(
                    "mma.sync.aligned.m16n8k16.row.col.f32.f16.f16.f32 "
                    "{%0,%1,%2,%3}, {%4,%5,%6,%7}, {%8,%9}, {%0,%1,%2,%3};"
                    : "+f"(acc[mi][ni][0]), "+f"(acc[mi][ni][1]),
                      "+f"(acc[mi][ni][2]), "+f"(acc[mi][ni][3])
                    : "r"(a[mi][0]), "r"(a[mi][1]), "r"(a[mi][2]), "r"(a[mi][3]),
                      "r"(b[ni][0]), "r"(b[ni][1]));
            }
    }

    const int g = lane >> 2, t = lane & 3;
#pragma unroll
    for (int mi = 0; mi < 2; mi++) {
#pragma unroll
        for (int ni = 0; ni < 8; ni++) {
            int col = warpN * 64 + ni * 8 + t * 2;
            float b0 = bs[col], b1 = bs[col + 1];
            int r0 = rowBase + warpM * 32 + mi * 16 + g;
            int r1 = r0 + 8;
            if (r0 < NN)
                Y[(size_t)r0 * 64 + (col >> 1)] =
                    __floats2half2_rn(acc[mi][ni][0] + b0, acc[mi][ni][1] + b1);
            if (r1 < NN)
                Y[(size_t)r1 * 64 + (col >> 1)] =
                    __floats2half2_rn(acc[mi][ni][2] + b0, acc[mi][ni][3] + b1);
        }
    }
}

// ------- Fused score+gate: tile = 64 nodes x 2 views (128 MMA rows) -------
__global__ void __launch_bounds__(256, 2) mma_scoregate_kernel(
    const float4* __restrict__ x4,    // fp32 [2N,128]
    const uint4* __restrict__ Bt,     // fw1^T fp16
    const float* __restrict__ b1,
    const float* __restrict__ w2,
    uint4* __restrict__ fused)        // fp16 [N,128]
{
    __half* sm = (__half*)dynsm;
    __half* sA = sm;
    __half* sB = sm + 128 * AST;
    __shared__ float b1s[DD];
    __shared__ float w2s[DD];
    __shared__ float ssc[2][128];

    const int tid = threadIdx.x;
    const int lane = tid & 31;
    const int warp = tid >> 5;
    const int warpM = warp & 3;
    const int warpN = warp >> 2;
    const int nodeBase = blockIdx.x * 64;

    for (int i = tid; i < 2048; i += 256) {
        int r = i >> 4, c = i & 15;
        int view = r >> 6;
        int node = nodeBase + (r & 63);
        uint4 v = make_uint4(0u, 0u, 0u, 0u);
        if (node < NN) {
            size_t gr = (size_t)view * NN + node;
            float4 lo = __ldg(&x4[gr * 32 + c * 2]);
            float4 hi = __ldg(&x4[gr * 32 + c * 2 + 1]);
            __half2 h0 = __floats2half2_rn(lo.x, lo.y);
            __half2 h1 = __floats2half2_rn(lo.z, lo.w);
            __half2 h2 = __floats2half2_rn(hi.x, hi.y);
            __half2 h3 = __floats2half2_rn(hi.z, hi.w);
            v.x = *(unsigned*)&h0; v.y = *(unsigned*)&h1;
            v.z = *(unsigned*)&h2; v.w = *(unsigned*)&h3;
        }
        *(uint4*)&sA[r * AST + c * 8] = v;
    }
    for (int i = tid; i < 2048; i += 256) {
        int r = i >> 4, c = i & 15;
        *(uint4*)&sB[r * AST + c * 8] = __ldg(&Bt[i]);
    }
    if (tid < 128) {
        b1s[tid] = __ldg(&b1[tid]);
        w2s[tid] = __ldg(&w2[tid]);
    }
    __syncthreads();

    float acc[2][8][4];
#pragma unroll
    for (int mi = 0; mi < 2; mi++)
#pragma unroll
        for (int ni = 0; ni < 8; ni++)
#pragma unroll
            for (int q = 0; q < 4; q++) acc[mi][ni][q] = 0.f;

#pragma unroll
    for (int k0 = 0; k0 < 128; k0 += 16) {
        uint32_t a[2][4];
#pragma unroll
        for (int mi = 0; mi < 2; mi++) {
            int row = warpM * 32 + mi * 16 + (lane & 15);
            int col = k0 + ((lane >> 4) << 3);
            uint32_t addr = smem_u32(&sA[row * AST + col]);
            asm volatile("ldmatrix.sync.aligned.m8n8.x4.shared.b16 {%0,%1,%2,%3}, [%4];"
                         : "=r"(a[mi][0]), "=r"(a[mi][1]), "=r"(a[mi][2]), "=r"(a[mi][3])
                         : "r"(addr));
        }
        uint32_t b[8][2];
#pragma unroll
        for (int ni = 0; ni < 8; ni++) {
            int n = warpN * 64 + ni * 8 + (lane & 7);
            int col = k0 + (((lane >> 3) & 1) << 3);
            uint32_t addr = smem_u32(&sB[n * AST + col]);
            asm volatile("ldmatrix.sync.aligned.m8n8.x2.shared.b16 {%0,%1}, [%2];"
                         : "=r"(b[ni][0]), "=r"(b[ni][1]) : "r"(addr));
        }
#pragma unroll
        for (int mi = 0; mi < 2; mi++)
#pragma unroll
            for (int ni = 0; ni < 8; ni++) {
                asm volatile(
                    "mma.sync.aligned.m16n8k16.row.col.f32.f16.f16.f32 "
                    "{%0,%1,%2,%3}, {%4,%5,%6,%7}, {%8,%9}, {%0,%1,%2,%3};"
                    : "+f"(acc[mi][ni][0]), "+f"(acc[mi][ni][1]),
                      "+f"(acc[mi][ni][2]), "+f"(acc[mi][ni][3])
                    : "r"(a[mi][0]), "r"(a[mi][1]), "r"(a[mi][2]), "r"(a[mi][3]),
                      "r"(b[ni][0]), "r"(b[ni][1]));
            }
    }

    const int g = lane >> 2, t = lane & 3;
#pragma unroll
    for (int mi = 0; mi < 2; mi++) {
        float pr0 = 0.f, pr1 = 0.f;
#pragma unroll
        for (int ni = 0; ni < 8; ni++) {
            int col = warpN * 64 + ni * 8 + t * 2;
            float w0 = w2s[col], w1 = w2s[col + 1];
            float c0 = b1s[col], c1 = b1s[col + 1];
            pr0 += tanhf(acc[mi][ni][0] + c0) * w0 + tanhf(acc[mi][ni][1] + c1) * w1;
            pr1 += tanhf(acc[mi][ni][2] + c0) * w0 + tanhf(acc[mi][ni][3] + c1) * w1;
        }
        pr0 += __shfl_xor_sync(0xffffffffu, pr0, 1);
        pr0 += __shfl_xor_sync(0xffffffffu, pr0, 2);
        pr1 += __shfl_xor_sync(0xffffffffu, pr1, 1);
        pr1 += __shfl_xor_sync(0xffffffffu, pr1, 2);
        if (t == 0) {
            ssc[warpN][warpM * 32 + mi * 16 + g] = pr0;
            ssc[warpN][warpM * 32 + mi * 16 + g + 8] = pr1;
        }
    }
    __syncthreads();

    int j = tid >> 2, q = tid & 3;
    int node = nodeBase + j;
    if (node < NN) {
        float s0 = ssc[0][j] + ssc[1][j];
        float s1 = ssc[0][64 + j] + ssc[1][64 + j];
        float m = fmaxf(s0, s1);
        float e0 = expf(s0 - m), e1 = expf(s1 - m);
        float inv = 1.f / (e0 + e1);
        float g0 = e0 * inv, g1 = e1 * inv;
#pragma unroll
        for (int c = q * 4; c < q * 4 + 4; c++) {
            uint4 av = *(uint4*)&sA[j * AST + c * 8];
            uint4 bv = *(uint4*)&sA[(64 + j) * AST + c * 8];
            uint4 o;
            const unsigned* ap = &av.x;
            const unsigned* bp = &bv.x;
            unsigned* op = &o.x;
#pragma unroll
            for (int w = 0; w < 4; w++) {
                float2 fa = __half22float2(*(__half2*)&ap[w]);
                float2 fb = __half22float2(*(__half2*)&bp[w]);
                __half2 h = __floats2half2_rn(g0 * fa.x + g1 * fb.x,
                                              g0 * fa.y + g1 * fb.y);
                op[w] = *(unsigned*)&h;
            }
            fused[(size_t)node * 16 + c] = o;
        }
    }
}

// ---------------- bucket build: clear counters, then direct scatter ----------------
__global__ void clear_cnt_kernel() {
    int i = blockIdx.x * blockDim.x + threadIdx.x;
    if (i < 3 * NN / 4) ((int4*)g_cnt)[i] = make_int4(0, 0, 0, 0);
}

// direct scatter into padded row buckets: 8 edges per thread, 4B packed payload
__global__ void scatter1_kernel(const int* __restrict__ rows, const int* __restrict__ cols,
                                const float* __restrict__ vals, int m) {
    int* cnt = g_cnt[m];
    unsigned* epack = g_epack[m];
    int i = (blockIdx.x * blockDim.x + threadIdx.x) * 8;
    if (i + 7 < EE) {
        int4 rA = __ldg((const int4*)(rows + i));
        int4 rB = __ldg((const int4*)(rows + i + 4));
        int4 cA = __ldg((const int4*)(cols + i));
        int4 cB = __ldg((const int4*)(cols + i + 4));
        float4 vA = __ldg((const float4*)(vals + i));
        float4 vB = __ldg((const float4*)(vals + i + 4));
        int p0 = atomicAdd(&cnt[rA.x], 1);
        int p1 = atomicAdd(&cnt[rA.y], 1);
        int p2 = atomicAdd(&cnt[rA.z], 1);
        int p3 = atomicAdd(&cnt[rA.w], 1);
        int p4 = atomicAdd(&cnt[rB.x], 1);
        int p5 = atomicAdd(&cnt[rB.y], 1);
        int p6 = atomicAdd(&cnt[rB.z], 1);
        int p7 = atomicAdd(&cnt[rB.w], 1);
        epack[(size_t)rA.x * RCAP + p0] = eenc(cA.x, vA.x);
        epack[(size_t)rA.y * RCAP + p1] = eenc(cA.y, vA.y);
        epack[(size_t)rA.z * RCAP + p2] = eenc(cA.z, vA.z);
        epack[(size_t)rA.w * RCAP + p3] = eenc(cA.w, vA.w);
        epack[(size_t)rB.x * RCAP + p4] = eenc(cB.x, vB.x);
        epack[(size_t)rB.y * RCAP + p5] = eenc(cB.y, vB.y);
        epack[(size_t)rB.z * RCAP + p6] = eenc(cB.z, vB.z);
        epack[(size_t)rB.w * RCAP + p7] = eenc(cB.w, vB.w);
    } else {
        for (int j = i; j < EE; j++) {
            int rr = rows[j];
            int p = atomicAdd(&cnt[rr], 1);
            epack[(size_t)rr * RCAP + p] = eenc(cols[j], vals[j]);
        }
    }
}

// ---------------- SpMM: warp per row, bucket layout, packed 4B meta ----------
// addH: optional fp16 vector added into acc epilogue
__global__ void spmm_kernel(const int* __restrict__ cnt, const unsigned* __restrict__ ep,
                            const uint4* __restrict__ x,
                            float* __restrict__ yF, uint2* __restrict__ yH,
                            float* __restrict__ acc, const uint2* __restrict__ addH,
                            int relu) {
    int gwarp = (blockIdx.x * blockDim.x + threadIdx.x) >> 5;
    int lane  = threadIdx.x & 31;
    int hr = lane >> 4;        // half-warp id
    int li = lane & 15;        // 16B chunk within row
    int beg = gwarp * RCAP;
    int end = beg + cnt[gwarp];

    float a8[8];
#pragma unroll
    for (int k = 0; k < 8; k++) a8[k] = 0.f;

    int e = beg;
    // main: 4 edges/iter; each half-warp loads ONE uint2 = its two packed edges
    for (; e + 3 < end; e += 4) {
        uint2 mm = __ldg((const uint2*)&ep[e + 2 * hr]);
        int c0, c1; float w0, w1;
        edec(mm.x, c0, w0);
        edec(mm.y, c1, w1);
        uint4 v0 = __ldg(&x[(size_t)c0 * 16 + li]);
        uint4 v1 = __ldg(&x[(size_t)c1 * 16 + li]);
        float2 f0 = __half22float2(*(__half2*)&v0.x);
        float2 f1 = __half22float2(*(__half2*)&v0.y);
        float2 f2 = __half22float2(*(__half2*)&v0.z);
        float2 f3 = __half22float2(*(__half2*)&v0.w);
        a8[0] += w0 * f0.x; a8[1] += w0 * f0.y; a8[2] += w0 * f1.x; a8[3] += w0 * f1.y;
        a8[4] += w0 * f2.x; a8[5] += w0 * f2.y; a8[6] += w0 * f3.x; a8[7] += w0 * f3.y;
        f0 = __half22float2(*(__half2*)&v1.x);
        f1 = __half22float2(*(__half2*)&v1.y);
        f2 = __half22float2(*(__half2*)&v1.z);
        f3 = __half22float2(*(__half2*)&v1.w);
        a8[0] += w1 * f0.x; a8[1] += w1 * f0.y; a8[2] += w1 * f1.x; a8[3] += w1 * f1.y;
        a8[4] += w1 * f2.x; a8[5] += w1 * f2.y; a8[6] += w1 * f3.x; a8[7] += w1 * f3.y;
    }
    // 2-edge tail
    for (; e + 1 < end; e += 2) {
        unsigned mm = __ldg(&ep[e + hr]);
        int c0; float w0;
        edec(mm, c0, w0);
        uint4 v0 = __ldg(&x[(size_t)c0 * 16 + li]);
        float2 f0 = __half22float2(*(__half2*)&v0.x);
        float2 f1 = __half22float2(*(__half2*)&v0.y);
        float2 f2 = __half22float2(*(__half2*)&v0.z);
        float2 f3 = __half22float2(*(__half2*)&v0.w);
        a8[0] += w0 * f0.x; a8[1] += w0 * f0.y; a8[2] += w0 * f1.x; a8[3] += w0 * f1.y;
        a8[4] += w0 * f2.x; a8[5] += w0 * f2.y; a8[6] += w0 * f3.x; a8[7] += w0 * f3.y;
    }
    // final single edge
    if (e < end && hr == 0) {
        unsigned mm = __ldg(&ep[e]);
        int c0; float w0;
        edec(mm, c0, w0);
        uint4 v0 = __ldg(&x[(size_t)c0 * 16 + li]);
        float2 f0 = __half22float2(*(__half2*)&v0.x);
        float2 f1 = __half22float2(*(__half2*)&v0.y);
        float2 f2 = __half22float2(*(__half2*)&v0.z);
        float2 f3 = __half22float2(*(__half2*)&v0.w);
        a8[0] += w0 * f0.x; a8[1] += w0 * f0.y; a8[2] += w0 * f1.x; a8[3] += w0 * f1.y;
        a8[4] += w0 * f2.x; a8[5] += w0 * f2.y; a8[6] += w0 * f3.x; a8[7] += w0 * f3.y;
    }

#pragma unroll
    for (int k = 0; k < 8; k++) a8[k] += __shfl_xor_sync(0xffffffffu, a8[k], 16);

    float4 r;
    r.x = a8[hr * 4 + 0]; r.y = a8[hr * 4 + 1];
    r.z = a8[hr * 4 + 2]; r.w = a8[hr * 4 + 3];
    if (relu) {
        r.x = fmaxf(r.x, 0.f); r.y = fmaxf(r.y, 0.f);
        r.z = fmaxf(r.z, 0.f); r.w = fmaxf(r.w, 0.f);
    }
    size_t oi = (size_t)gwarp * 32 + li * 2 + hr;
    if (yF) ((float4*)yF)[oi] = r;
    if (yH) {
        __half2 h0 = __floats2half2_rn(r.x, r.y);
        __half2 h1 = __floats2half2_rn(r.z, r.w);
        uint2 hv;
        hv.x = *(unsigned*)&h0; hv.y = *(unsigned*)&h1;
        yH[oi] = hv;
    }
    if (acc) {
        float4 o = ((float4*)acc)[oi];
        if (addH) {
            uint2 av = __ldg(&addH[oi]);
            float2 a0 = __half22float2(*(__half2*)&av.x);
            float2 a1 = __half22float2(*(__half2*)&av.y);
            o.x += a0.x; o.y += a0.y; o.z += a1.x; o.w += a1.y;
        }
        o.x += r.x; o.y += r.y; o.z += r.z; o.w += r.w;
        ((float4*)acc)[oi] = o;
    }
}

// ---------------- host ----------------
extern "C" void kernel_launch(void* const* d_in, const int* in_sizes, int n_in,
                              void* d_out, int out_size) {
    const float* x    = (const float*)d_in[0];
    const float* fw1  = (const float*)d_in[1];
    const float* fb1  = (const float*)d_in[2];
    const float* fw2  = (const float*)d_in[3];
    const float* fb2  = (const float*)d_in[4];
    const float* hgw  = (const float*)d_in[5];
    const float* lgw  = (const float*)d_in[6];
    const float* lgb  = (const float*)d_in[7];
    const float* c1v  = (const float*)d_in[8];
    const float* c2v  = (const float*)d_in[9];
    const float* lgv  = (const float*)d_in[10];
    const int* c1r = (const int*)d_in[11];
    const int* c1c = (const int*)d_in[12];
    const int* c2r = (const int*)d_in[13];
    const int* c2c = (const int*)d_in[14];
    const int* lgr = (const int*)d_in[15];
    const int* lgc = (const int*)d_in[16];
    float* out  = (float*)d_out;              // [2N, D]
    float* out2 = out + (size_t)NN * DD;
    (void)fb2;                                 // softmax-invariant

    __half2 *h16a, *h16b;
    int *cntBase;
    unsigned *epackBase;
    __half *wtBase;
    cudaGetSymbolAddress((void**)&h16a, g_h16a);
    cudaGetSymbolAddress((void**)&h16b, g_h16b);
    cudaGetSymbolAddress((void**)&cntBase, g_cnt);
    cudaGetSymbolAddress((void**)&epackBase, g_epack);
    cudaGetSymbolAddress((void**)&wtBase, g_wt);

    int* cnt[3];
    unsigned* epack[3];
    for (int m = 0; m < 3; m++) {
        cnt[m]   = cntBase + (size_t)m * NN;
        epack[m] = epackBase + (size_t)m * NN * RCAP;
    }
    const uint4* wt[6];
    for (int m = 0; m < 6; m++) wt[m] = (const uint4*)(wtBase + (size_t)m * DD * DD);

    const size_t smemMMA = 2 * 128 * AST * sizeof(__half) + DD * sizeof(float);   // ~70 KB
    cudaFuncSetAttribute(mma_linear_kernel, cudaFuncAttributeMaxDynamicSharedMemorySize, (int)smemMMA);
    cudaFuncSetAttribute(mma_scoregate_kernel, cudaFuncAttributeMaxDynamicSharedMemorySize, (int)smemMMA);

    const int SPB = (NN * 32 + 127) / 128;    // spmm: 128-thread blocks (4 warps)
    const int MB  = (NN + 127) / 128;         // mma tile grid
    const int SG  = (NN + 63) / 64;           // scoregate grid

    // ---- lazily-created side stream + events (host-side resources only) ----
    static cudaStream_t sCsr = nullptr;
    static cudaEvent_t evFork = nullptr, evC1 = nullptr, evC2 = nullptr, evC3 = nullptr;
    if (sCsr == nullptr) {
        cudaStreamCreateWithFlags(&sCsr, cudaStreamNonBlocking);
        cudaEventCreateWithFlags(&evFork, cudaEventDisableTiming);
        cudaEventCreateWithFlags(&evC1, cudaEventDisableTiming);
        cudaEventCreateWithFlags(&evC2, cudaEventDisableTiming);
        cudaEventCreateWithFlags(&evC3, cudaEventDisableTiming);
    }

    // fork the bucket-build stream off the main (capture) stream
    cudaEventRecord(evFork, 0);
    cudaStreamWaitEvent(sCsr, evFork, 0);

    // ---- bucket builds (per matrix) on side stream ----
    const int* rr[3] = { c1r, c2r, lgr };
    const int* cc[3] = { c1c, c2c, lgc };
    const float* vv[3] = { c1v, c2v, lgv };
    cudaEvent_t evDone[3] = { evC1, evC2, evC3 };
    clear_cnt_kernel<<<(3 * NN / 4 + 255) / 256, 256, 0, sCsr>>>();
    for (int m = 0; m < 3; m++) {
        scatter1_kernel<<<(EE / 8 + 255) / 256, 256, 0, sCsr>>>(rr[m], cc[m], vv[m], m);
        cudaEventRecord(evDone[m], sCsr);
    }

    // ---- main stream: weight prep + fused score/gate -> h16b ----
    wprep_kernel<<<dim3(64, 6), 256>>>(hgw, lgw, fw1);
    mma_scoregate_kernel<<<SG, 256, smemMMA>>>((const float4*)x, wt[5], fb1, fw2, (uint4*)h16b);

    // ---- HypergraphConv ----
    mma_linear_kernel<<<MB, 256, smemMMA>>>((const uint4*)h16b, wt[0], nullptr, h16a);
    cudaStreamWaitEvent(0, evC1, 0);          // coef1 buckets ready
    spmm_kernel<<<SPB, 128>>>(cnt[0], epack[0], (const uint4*)h16a, nullptr, (uint2*)h16b, nullptr, nullptr, 1);
    mma_linear_kernel<<<MB, 256, smemMMA>>>((const uint4*)h16b, wt[1], nullptr, h16a);
    spmm_kernel<<<SPB, 128>>>(cnt[0], epack[0], (const uint4*)h16a, nullptr, (uint2*)h16b, nullptr, nullptr, 1);
    mma_linear_kernel<<<MB, 256, smemMMA>>>((const uint4*)h16b, wt[2], nullptr, h16a);
    // h -> out (fp32) + fp16 shadow h16b
    spmm_kernel<<<SPB, 128>>>(cnt[0], epack[0], (const uint4*)h16a, out, (uint2*)h16b, nullptr, nullptr, 1);
    cudaStreamWaitEvent(0, evC2, 0);          // coef2 buckets ready
    // y = relu(spmm(coef2, h)): y fp32 -> out2 (init), y fp16 -> h16a (cur)
    spmm_kernel<<<SPB, 128>>>(cnt[1], epack[1], (const uint4*)h16b, out2, (uint2*)h16a, nullptr, nullptr, 1);

    // ---- LineConv ----
    mma_linear_kernel<<<MB, 256, smemMMA>>>((const uint4*)h16a, wt[3], lgb, h16b);
    cudaStreamWaitEvent(0, evC3, 0);          // lg buckets ready
    // cur1 -> h16a (fp16 only, no RMW)
    spmm_kernel<<<SPB, 128>>>(cnt[2], epack[2], (const uint4*)h16b, nullptr, (uint2*)h16a, nullptr, nullptr, 0);
    mma_linear_kernel<<<MB, 256, smemMMA>>>((const uint4*)h16a, wt[4], lgb + DD, h16b);
    // cur2 + fused final accumulation: out2 = out2(y) + cur1(h16a) + cur2
    spmm_kernel<<<SPB, 128>>>(cnt[2], epack[2], (const uint4*)h16b, nullptr, nullptr, out2, (const uint2*)h16a, 0);
}